// round 14
// baseline (speedup 1.0000x reference)
#include <cuda_runtime.h>
#include <cuda_bf16.h>
#include <cstdint>

// Problem constants
#define PB 8
#define PS 4096
#define PD 768
#define PN 64
#define D4 (PD / 4)            // 192 float4 per token row
#define NSEG (PB * PN)         // 512 segments
#define CH 32                  // tokens per chunk-block
#define NCHUNK (PS / CH)       // 128 chunks per batch
#define OUT_VEC_ELEMS ((size_t)PB * 2 * PN * PD)   // 786432
#define GRP 8                  // front-batched load group

// Direct per-segment results (only written when a segment fits in one chunk)
__device__ float g_sums[NSEG * PD];
__device__ float g_cnts[NSEG * PD];
// Boundary partials: [b][chunk][2][D].  slot 0 = run extending left of chunk
// (incl. full-chunk middle runs), slot 1 = run extending right only.
__device__ float g_psum[PB * NCHUNK * 2 * PD];
__device__ float g_pcnt[PB * NCHUNK * 2 * PD];

// per-batch completion counters (zero-init; reset by epilogue block each call)
__device__ int g_done[PB];

// ---------------------------------------------------------------------------
// cheap 2-warp shuffle prefix scan of this batch's 64 lengths into s_ends
// ---------------------------------------------------------------------------
__device__ __forceinline__ void scan_ends(const int* __restrict__ lens, int b,
                                          int tid, int* s_ends, int* s_w0tot) {
    if (tid < PN) {
        const int lane = tid & 31;
        int x = lens[b * PN + tid];
        #pragma unroll
        for (int off = 1; off < 32; off <<= 1) {
            int y = __shfl_up_sync(0xFFFFFFFFu, x, off);
            if (lane >= off) x += y;
        }
        if (tid == 31) *s_w0tot = x;
        s_ends[tid] = x;          // warp-local inclusive scan
    }
    __syncthreads();
    if (tid >= 32 && tid < PN) s_ends[tid] += *s_w0tot;
    __syncthreads();
}

// flush helper: store a run's partial to its unique slot
__device__ __forceinline__ void flush_run(
    int slot, int tid, const float4& acc, const float4& cnt)
{
    float4* sp = (slot < NSEG)
        ? reinterpret_cast<float4*>(g_sums) + slot * D4 + tid
        : reinterpret_cast<float4*>(g_psum) + (slot - NSEG) * D4 + tid;
    float4* cp = (slot < NSEG)
        ? reinterpret_cast<float4*>(g_cnts) + slot * D4 + tid
        : reinterpret_cast<float4*>(g_pcnt) + (slot - NSEG) * D4 + tid;
    *sp = acc;
    *cp = cnt;
}

// ---------------------------------------------------------------------------
// Fused kernel: balanced accumulate (one block per 32-token chunk) + rep
// gather + per-batch last-block epilogue (no spinning, no co-residency need).
// ---------------------------------------------------------------------------
__global__ __launch_bounds__(192, 5) void fused_kernel(
    const float* __restrict__ wv,
    const int* __restrict__ lens,
    const int* __restrict__ ids,
    const float* __restrict__ rmask,
    const float* __restrict__ lmask,
    float* __restrict__ out)
{
    __shared__ int s_ends[PN];
    __shared__ int s_w0tot;
    __shared__ int s_last;
    const int blk = blockIdx.x;
    const int b = blk >> 7;              // blk / NCHUNK
    const int c = blk & (NCHUNK - 1);
    const int tid = threadIdx.x;

    scan_ends(lens, b, tid, s_ends, &s_w0tot);

    const int t0 = c * CH;
    const int t1 = t0 + CH;

    const float4* base = reinterpret_cast<const float4*>(wv) +
                         (size_t)b * PS * D4 + tid;

    // ---- rep-token gather (first PN chunks of each batch handle one n) ----
    if (c < PN) {
        const int n = c;
        const int id = ids[b * PN + n];
        const float rm = rmask[b * PN + n];
        float4 v = reinterpret_cast<const float4*>(wv)[((size_t)b * PS + id) * D4 + tid];
        v.x *= rm; v.y *= rm; v.z *= rm; v.w *= rm;
        reinterpret_cast<float4*>(out)[((size_t)b * (2 * PN) + n) * D4 + tid] = v;
        if (tid == 0) {
            float* outm = out + OUT_VEC_ELEMS;
            outm[b * (2 * PN) + n]      = rm;
            outm[b * (2 * PN) + PN + n] = lmask[b * PN + n];
        }
    }

    // first segment containing token t0
    int seg = 0;
    while (s_ends[seg] <= t0) seg++;
    int nend = s_ends[seg];

    float4 acc = make_float4(0.f, 0.f, 0.f, 0.f);
    float4 mn  = make_float4(1.f, 1.f, 1.f, 1.f);
    int rs = t0;                         // current run start

    #pragma unroll
    for (int g = 0; g < CH / GRP; g++) {
        const int k0 = t0 + g * GRP;
        // front-batched loads: 8 consecutive LDG.128, no consumer between
        float4 w0 = base[(size_t)(k0 + 0) * D4];
        float4 w1 = base[(size_t)(k0 + 1) * D4];
        float4 w2 = base[(size_t)(k0 + 2) * D4];
        float4 w3 = base[(size_t)(k0 + 3) * D4];
        float4 w4 = base[(size_t)(k0 + 4) * D4];
        float4 w5 = base[(size_t)(k0 + 5) * D4];
        float4 w6 = base[(size_t)(k0 + 6) * D4];
        float4 w7 = base[(size_t)(k0 + 7) * D4];

        #pragma unroll
        for (int j = 0; j < GRP; j++) {
            const int k = k0 + j;
            float4 v;
            switch (j) {
                case 0: v = w0; break; case 1: v = w1; break;
                case 2: v = w2; break; case 3: v = w3; break;
                case 4: v = w4; break; case 5: v = w5; break;
                case 6: v = w6; break; default: v = w7; break;
            }
            acc.x += v.x; acc.y += v.y; acc.z += v.z; acc.w += v.w;
            mn.x = fminf(mn.x, fabsf(v.x));
            mn.y = fminf(mn.y, fabsf(v.y));
            mn.z = fminf(mn.z, fabsf(v.z));
            mn.w = fminf(mn.w, fabsf(v.w));

            if (k + 1 == nend) {
                // ---- flush run [rs, k+1) (ends inside this chunk) ----
                const int ke = k + 1;
                const float rl = (float)(ke - rs);
                float4 cnt = make_float4(rl, rl, rl, rl);
                if (!(mn.x > 0.f && mn.y > 0.f && mn.z > 0.f && mn.w > 0.f)) {
                    cnt = make_float4(0.f, 0.f, 0.f, 0.f);
                    for (int q = rs; q < ke; q++) {
                        float4 w = base[(size_t)q * D4];
                        cnt.x += (w.x != 0.f);
                        cnt.y += (w.y != 0.f);
                        cnt.z += (w.z != 0.f);
                        cnt.w += (w.w != 0.f);
                    }
                }
                const int seg_start = seg ? s_ends[seg - 1] : 0;
                const int slot = (seg_start < t0)
                    ? NSEG + (b * NCHUNK + c) * 2 + 0
                    : b * PN + seg;
                flush_run(slot, tid, acc, cnt);

                acc = make_float4(0.f, 0.f, 0.f, 0.f);
                mn  = make_float4(1.f, 1.f, 1.f, 1.f);
                rs = ke;
                if (ke < t1) {
                    do { seg++; } while (seg < PN && s_ends[seg] <= ke);
                    nend = s_ends[seg];
                }
            }
        }
    }

    // ---- trailing run extending past the chunk's right edge ----
    if (rs < t1) {
        const float rl = (float)(t1 - rs);
        float4 cnt = make_float4(rl, rl, rl, rl);
        if (!(mn.x > 0.f && mn.y > 0.f && mn.z > 0.f && mn.w > 0.f)) {
            cnt = make_float4(0.f, 0.f, 0.f, 0.f);
            for (int q = rs; q < t1; q++) {
                float4 w = base[(size_t)q * D4];
                cnt.x += (w.x != 0.f);
                cnt.y += (w.y != 0.f);
                cnt.z += (w.z != 0.f);
                cnt.w += (w.w != 0.f);
            }
        }
        const int seg_start = seg ? s_ends[seg - 1] : 0;
        const int slot = (seg_start < t0)
            ? NSEG + (b * NCHUNK + c) * 2 + 0   // spans whole chunk
            : NSEG + (b * NCHUNK + c) * 2 + 1;  // starts here, extends right
        flush_run(slot, tid, acc, cnt);
    }

    // ---- completion: last block of this batch runs the epilogue ----
    __threadfence();
    __syncthreads();
    if (tid == 0) {
        int old = atomicAdd(&g_done[b], 1);
        s_last = (old == NCHUNK - 1);
        if (s_last) g_done[b] = 0;       // reset for next graph replay
    }
    __syncthreads();
    if (!s_last) return;
    __threadfence();   // acquire: all partials of this batch now visible

    // ---- epilogue: finalize all 64 segments of batch b ----
    for (int n = 0; n < PN; n++) {
        const int start = n ? s_ends[n - 1] : 0;
        const int end   = s_ends[n];

        float4 s  = make_float4(0.f, 0.f, 0.f, 0.f);
        float4 cc = make_float4(0.f, 0.f, 0.f, 0.f);

        if (end > start) {
            const int c0 = start >> 5;           // start / CH
            const int c1 = (end - 1) >> 5;
            if (c0 == c1) {
                s  = reinterpret_cast<const float4*>(g_sums)[(b * PN + n) * D4 + tid];
                cc = reinterpret_cast<const float4*>(g_cnts)[(b * PN + n) * D4 + tid];
            } else {
                const float4* ps = reinterpret_cast<const float4*>(g_psum);
                const float4* pc = reinterpret_cast<const float4*>(g_pcnt);
                {
                    float4 a = ps[((b * NCHUNK + c0) * 2 + 1) * D4 + tid];
                    float4 d = pc[((b * NCHUNK + c0) * 2 + 1) * D4 + tid];
                    s.x += a.x; s.y += a.y; s.z += a.z; s.w += a.w;
                    cc.x += d.x; cc.y += d.y; cc.z += d.z; cc.w += d.w;
                }
                for (int cj = c0 + 1; cj <= c1; cj++) {
                    float4 a = ps[((b * NCHUNK + cj) * 2 + 0) * D4 + tid];
                    float4 d = pc[((b * NCHUNK + cj) * 2 + 0) * D4 + tid];
                    s.x += a.x; s.y += a.y; s.z += a.z; s.w += a.w;
                    cc.x += d.x; cc.y += d.y; cc.z += d.z; cc.w += d.w;
                }
            }
        }

        // block-reduce total nonzero count (for all_zero fallback)
        float tot = cc.x + cc.y + cc.z + cc.w;
        #pragma unroll
        for (int off = 16; off > 0; off >>= 1)
            tot += __shfl_down_sync(0xFFFFFFFFu, tot, off);
        __shared__ float warp_tot[6];
        const int wid = tid >> 5, lid = tid & 31;
        if (lid == 0) warp_tot[wid] = tot;
        __syncthreads();
        const float total = warp_tot[0] + warp_tot[1] + warp_tot[2] +
                            warp_tot[3] + warp_tot[4] + warp_tot[5];
        __syncthreads();   // warp_tot reused next iteration

        float4 mean;
        mean.x = s.x / fmaxf(cc.x, 1.f);
        mean.y = s.y / fmaxf(cc.y, 1.f);
        mean.z = s.z / fmaxf(cc.z, 1.f);
        mean.w = s.w / fmaxf(cc.w, 1.f);
        if (total == 0.f)
            mean = reinterpret_cast<const float4*>(wv)[tid];   // wv[0,0,:]

        const float lm = lmask[b * PN + n];
        float4 om;
        om.x = mean.x * lm; om.y = mean.y * lm;
        om.z = mean.z * lm; om.w = mean.w * lm;
        reinterpret_cast<float4*>(out)[((size_t)b * (2 * PN) + PN + n) * D4 + tid] = om;
    }
}

// ---------------------------------------------------------------------------
extern "C" void kernel_launch(void* const* d_in, const int* in_sizes, int n_in,
                              void* d_out, int out_size) {
    const float* wv    = (const float*)d_in[0];  // [B,S,D] f32
    const int*   ids   = (const int*)d_in[1];    // [B,N] i32
    const float* rmask = (const float*)d_in[2];  // [B,N] f32
    const int*   lens  = (const int*)d_in[3];    // [B,N] i32
    const float* lmask = (const float*)d_in[4];  // [B,N] f32
    float* out = (float*)d_out;

    fused_kernel<<<PB * NCHUNK, 192>>>(wv, lens, ids, rmask, lmask, out);
}

// round 17
// speedup vs baseline: 1.0085x; 1.0085x over previous
#include <cuda_runtime.h>
#include <cuda_bf16.h>
#include <cstdint>

// Problem constants
#define PB 8
#define PS 4096
#define PD 768
#define PN 64
#define D4 (PD / 4)            // 192 float4 per token row
#define NSEG (PB * PN)         // 512 segments
#define CH 64                  // tokens per chunk-block
#define NCHUNK (PS / CH)       // 64 chunks per batch
#define OUT_VEC_ELEMS ((size_t)PB * 2 * PN * PD)   // 786432
#define PF 4                   // prefetch ring depth (16 regs)

// Direct per-segment results (only written when a segment fits in one chunk)
__device__ float g_sums[NSEG * PD];
__device__ float g_cnts[NSEG * PD];
// Boundary partials: [b][chunk][2][D].  slot 0 = run extending left of chunk
// (incl. full-chunk middle runs), slot 1 = run extending right only.
__device__ float g_psum[PB * NCHUNK * 2 * PD];
__device__ float g_pcnt[PB * NCHUNK * 2 * PD];

// per-batch completion counters (zero-init; reset by epilogue block each call)
__device__ int g_done[PB];

// ---------------------------------------------------------------------------
// cheap 2-warp shuffle prefix scan of this batch's 64 lengths into s_ends
// ---------------------------------------------------------------------------
__device__ __forceinline__ void scan_ends(const int* __restrict__ lens, int b,
                                          int tid, int* s_ends, int* s_w0tot) {
    if (tid < PN) {
        const int lane = tid & 31;
        int x = lens[b * PN + tid];
        #pragma unroll
        for (int off = 1; off < 32; off <<= 1) {
            int y = __shfl_up_sync(0xFFFFFFFFu, x, off);
            if (lane >= off) x += y;
        }
        if (tid == 31) *s_w0tot = x;
        s_ends[tid] = x;          // warp-local inclusive scan
    }
    __syncthreads();
    if (tid >= 32 && tid < PN) s_ends[tid] += *s_w0tot;
    __syncthreads();
}

// flush helper: store a run's partial to its unique slot
__device__ __forceinline__ void flush_run(
    int slot, int tid, const float4& acc, const float4& cnt)
{
    float4* sp = (slot < NSEG)
        ? reinterpret_cast<float4*>(g_sums) + slot * D4 + tid
        : reinterpret_cast<float4*>(g_psum) + (slot - NSEG) * D4 + tid;
    float4* cp = (slot < NSEG)
        ? reinterpret_cast<float4*>(g_cnts) + slot * D4 + tid
        : reinterpret_cast<float4*>(g_pcnt) + (slot - NSEG) * D4 + tid;
    *sp = acc;
    *cp = cnt;
}

// ---------------------------------------------------------------------------
// Fused kernel: balanced accumulate (one block per 64-token chunk, 4-deep
// register ring) + rep gather + per-batch last-block epilogue (spin-free).
// ---------------------------------------------------------------------------
__global__ __launch_bounds__(192, 5) void fused_kernel(
    const float* __restrict__ wv,
    const int* __restrict__ lens,
    const int* __restrict__ ids,
    const float* __restrict__ rmask,
    const float* __restrict__ lmask,
    float* __restrict__ out)
{
    __shared__ int s_ends[PN];
    __shared__ int s_w0tot;
    __shared__ int s_last;
    const int blk = blockIdx.x;
    const int b = blk >> 6;              // blk / NCHUNK
    const int c = blk & (NCHUNK - 1);
    const int tid = threadIdx.x;

    scan_ends(lens, b, tid, s_ends, &s_w0tot);

    const int t0 = c * CH;
    const int t1 = t0 + CH;

    const float4* base = reinterpret_cast<const float4*>(wv) +
                         (size_t)b * PS * D4 + tid;

    // ---- prime the load ring for tokens t0 .. t0+PF-1 ----
    float4 buf[PF];
    #pragma unroll
    for (int j = 0; j < PF; j++)
        buf[j] = base[(size_t)(t0 + j) * D4];

    // ---- rep-token gather (independent; issued while ring loads fly) ----
    {
        const int n = c;                 // NCHUNK == PN
        const int id = ids[b * PN + n];
        const float rm = rmask[b * PN + n];
        float4 v = reinterpret_cast<const float4*>(wv)[((size_t)b * PS + id) * D4 + tid];
        v.x *= rm; v.y *= rm; v.z *= rm; v.w *= rm;
        reinterpret_cast<float4*>(out)[((size_t)b * (2 * PN) + n) * D4 + tid] = v;
        if (tid == 0) {
            float* outm = out + OUT_VEC_ELEMS;
            outm[b * (2 * PN) + n]      = rm;
            outm[b * (2 * PN) + PN + n] = lmask[b * PN + n];
        }
    }

    // first segment containing token t0
    int seg = 0;
    while (s_ends[seg] <= t0) seg++;
    int nend = s_ends[seg];

    float4 acc = make_float4(0.f, 0.f, 0.f, 0.f);
    float4 mn  = make_float4(1.f, 1.f, 1.f, 1.f);
    int rs = t0;                         // current run start

    for (int g = 0; g < CH / PF; g++) {
        const bool more = (g < CH / PF - 1);
        #pragma unroll
        for (int j = 0; j < PF; j++) {
            const int k = t0 + g * PF + j;
            const float4 v = buf[j];
            if (more) buf[j] = base[(size_t)(k + PF) * D4];   // refill ring

            acc.x += v.x; acc.y += v.y; acc.z += v.z; acc.w += v.w;
            mn.x = fminf(mn.x, fabsf(v.x));
            mn.y = fminf(mn.y, fabsf(v.y));
            mn.z = fminf(mn.z, fabsf(v.z));
            mn.w = fminf(mn.w, fabsf(v.w));

            if (k + 1 == nend) {
                // ---- flush run [rs, k+1) (ends inside this chunk) ----
                const int ke = k + 1;
                const float rl = (float)(ke - rs);
                float4 cnt = make_float4(rl, rl, rl, rl);
                if (!(mn.x > 0.f && mn.y > 0.f && mn.z > 0.f && mn.w > 0.f)) {
                    cnt = make_float4(0.f, 0.f, 0.f, 0.f);
                    for (int q = rs; q < ke; q++) {
                        float4 w = base[(size_t)q * D4];
                        cnt.x += (w.x != 0.f);
                        cnt.y += (w.y != 0.f);
                        cnt.z += (w.z != 0.f);
                        cnt.w += (w.w != 0.f);
                    }
                }
                const int seg_start = seg ? s_ends[seg - 1] : 0;
                const int slot = (seg_start < t0)
                    ? NSEG + (b * NCHUNK + c) * 2 + 0
                    : b * PN + seg;
                flush_run(slot, tid, acc, cnt);

                acc = make_float4(0.f, 0.f, 0.f, 0.f);
                mn  = make_float4(1.f, 1.f, 1.f, 1.f);
                rs = ke;
                if (ke < t1) {
                    do { seg++; } while (seg < PN && s_ends[seg] <= ke);
                    nend = s_ends[seg];
                }
            }
        }
    }

    // ---- trailing run extending past the chunk's right edge ----
    if (rs < t1) {
        const float rl = (float)(t1 - rs);
        float4 cnt = make_float4(rl, rl, rl, rl);
        if (!(mn.x > 0.f && mn.y > 0.f && mn.z > 0.f && mn.w > 0.f)) {
            cnt = make_float4(0.f, 0.f, 0.f, 0.f);
            for (int q = rs; q < t1; q++) {
                float4 w = base[(size_t)q * D4];
                cnt.x += (w.x != 0.f);
                cnt.y += (w.y != 0.f);
                cnt.z += (w.z != 0.f);
                cnt.w += (w.w != 0.f);
            }
        }
        const int seg_start = seg ? s_ends[seg - 1] : 0;
        const int slot = (seg_start < t0)
            ? NSEG + (b * NCHUNK + c) * 2 + 0   // spans whole chunk
            : NSEG + (b * NCHUNK + c) * 2 + 1;  // starts here, extends right
        flush_run(slot, tid, acc, cnt);
    }

    // ---- completion: last block of this batch runs the epilogue ----
    __threadfence();
    __syncthreads();
    if (tid == 0) {
        int old = atomicAdd(&g_done[b], 1);
        s_last = (old == NCHUNK - 1);
        if (s_last) g_done[b] = 0;       // reset for next graph replay
    }
    __syncthreads();
    if (!s_last) return;
    __threadfence();   // acquire: all partials of this batch now visible

    // ---- epilogue: finalize all 64 segments of batch b (L2-hot reads) ----
    for (int n = 0; n < PN; n++) {
        const int start = n ? s_ends[n - 1] : 0;
        const int end   = s_ends[n];

        float4 s  = make_float4(0.f, 0.f, 0.f, 0.f);
        float4 cc = make_float4(0.f, 0.f, 0.f, 0.f);

        if (end > start) {
            const int c0 = start >> 6;           // start / CH
            const int c1 = (end - 1) >> 6;
            if (c0 == c1) {
                s  = reinterpret_cast<const float4*>(g_sums)[(b * PN + n) * D4 + tid];
                cc = reinterpret_cast<const float4*>(g_cnts)[(b * PN + n) * D4 + tid];
            } else {
                const float4* ps = reinterpret_cast<const float4*>(g_psum);
                const float4* pc = reinterpret_cast<const float4*>(g_pcnt);
                {
                    float4 a = ps[((b * NCHUNK + c0) * 2 + 1) * D4 + tid];
                    float4 d = pc[((b * NCHUNK + c0) * 2 + 1) * D4 + tid];
                    s.x += a.x; s.y += a.y; s.z += a.z; s.w += a.w;
                    cc.x += d.x; cc.y += d.y; cc.z += d.z; cc.w += d.w;
                }
                for (int cj = c0 + 1; cj <= c1; cj++) {
                    float4 a = ps[((b * NCHUNK + cj) * 2 + 0) * D4 + tid];
                    float4 d = pc[((b * NCHUNK + cj) * 2 + 0) * D4 + tid];
                    s.x += a.x; s.y += a.y; s.z += a.z; s.w += a.w;
                    cc.x += d.x; cc.y += d.y; cc.z += d.z; cc.w += d.w;
                }
            }
        }

        // block-reduce total nonzero count (for all_zero fallback)
        float tot = cc.x + cc.y + cc.z + cc.w;
        #pragma unroll
        for (int off = 16; off > 0; off >>= 1)
            tot += __shfl_down_sync(0xFFFFFFFFu, tot, off);
        __shared__ float warp_tot[6];
        const int wid = tid >> 5, lid = tid & 31;
        if (lid == 0) warp_tot[wid] = tot;
        __syncthreads();
        const float total = warp_tot[0] + warp_tot[1] + warp_tot[2] +
                            warp_tot[3] + warp_tot[4] + warp_tot[5];
        __syncthreads();   // warp_tot reused next iteration

        float4 mean;
        mean.x = s.x / fmaxf(cc.x, 1.f);
        mean.y = s.y / fmaxf(cc.y, 1.f);
        mean.z = s.z / fmaxf(cc.z, 1.f);
        mean.w = s.w / fmaxf(cc.w, 1.f);
        if (total == 0.f)
            mean = reinterpret_cast<const float4*>(wv)[tid];   // wv[0,0,:]

        const float lm = lmask[b * PN + n];
        float4 om;
        om.x = mean.x * lm; om.y = mean.y * lm;
        om.z = mean.z * lm; om.w = mean.w * lm;
        reinterpret_cast<float4*>(out)[((size_t)b * (2 * PN) + PN + n) * D4 + tid] = om;
    }
}

// ---------------------------------------------------------------------------
extern "C" void kernel_launch(void* const* d_in, const int* in_sizes, int n_in,
                              void* d_out, int out_size) {
    const float* wv    = (const float*)d_in[0];  // [B,S,D] f32
    const int*   ids   = (const int*)d_in[1];    // [B,N] i32
    const float* rmask = (const float*)d_in[2];  // [B,N] f32
    const int*   lens  = (const int*)d_in[3];    // [B,N] i32
    const float* lmask = (const float*)d_in[4];  // [B,N] f32
    float* out = (float*)d_out;

    fused_kernel<<<PB * NCHUNK, 192>>>(wv, lens, ids, rmask, lmask, out);
}